// round 15
// baseline (speedup 1.0000x reference)
#include <cuda_runtime.h>
#include <cuda_fp16.h>
#include <string.h>

#define N_NODES   100000
#define N_EDGES   1600000
#define N_UNARY   16
#define N_BIN     4
#define N_CLAUSES 8

// Edge-stage gather table: u[:, 0:8] packed as fp16 (16 B per node row).
// 1.6 MB -> fully L2-resident; one divergent LDG.128 per gather side.
__device__ __half2 g_u16[N_NODES * 4];

// Clause weights in constant memory (filled per launch by an async D2D copy —
// graph-capturable memcpy node, no allocation).  Loads become uniform LDC,
// freeing registers and LSU slots in the edge hot loop.
__constant__ float c_ucw[8];
__constant__ float c_bcw[8];

// ---------------------------------------------------------------------------
// 256-bit coalesced ops (sm_100+)
// ---------------------------------------------------------------------------
__device__ __forceinline__ void ldg_v8(const float* __restrict__ p, float* r) {
    asm volatile("ld.global.nc.v8.f32 {%0,%1,%2,%3,%4,%5,%6,%7}, [%8];"
                 : "=f"(r[0]), "=f"(r[1]), "=f"(r[2]), "=f"(r[3]),
                   "=f"(r[4]), "=f"(r[5]), "=f"(r[6]), "=f"(r[7])
                 : "l"(p));
}
__device__ __forceinline__ void ldg_v8_cs(const float* __restrict__ p, float* r) {
    asm volatile("ld.global.cs.v8.f32 {%0,%1,%2,%3,%4,%5,%6,%7}, [%8];"
                 : "=f"(r[0]), "=f"(r[1]), "=f"(r[2]), "=f"(r[3]),
                   "=f"(r[4]), "=f"(r[5]), "=f"(r[6]), "=f"(r[7])
                 : "l"(p));
}
__device__ __forceinline__ void stg_v8(float* p, const float* r) {
    asm volatile("st.global.v8.f32 [%0], {%1,%2,%3,%4,%5,%6,%7,%8};"
                 :: "l"(p),
                    "f"(r[0]), "f"(r[1]), "f"(r[2]), "f"(r[3]),
                    "f"(r[4]), "f"(r[5]), "f"(r[6]), "f"(r[7]) : "memory");
}
__device__ __forceinline__ void stg_v8_cs(float* p, const float* r) {
    asm volatile("st.global.cs.v8.f32 [%0], {%1,%2,%3,%4,%5,%6,%7,%8};"
                 :: "l"(p),
                    "f"(r[0]), "f"(r[1]), "f"(r[2]), "f"(r[3]),
                    "f"(r[4]), "f"(r[5]), "f"(r[6]), "f"(r[7]) : "memory");
}

// ---------------------------------------------------------------------------
// Stage 1: u = unary + KENN(unary).  v8 streams (R13 winner).
// ---------------------------------------------------------------------------
__global__ void __launch_bounds__(256) node_kernel(
    const float* __restrict__ unary,
    float* __restrict__ out_u)
{
    int n = blockIdx.x * blockDim.x + threadIdx.x;
    if (n >= N_NODES) return;

    float x[16];
    ldg_v8(unary + (size_t)n * 16,     x);
    ldg_v8(unary + (size_t)n * 16 + 8, x + 8);

    float d[16];
    #pragma unroll
    for (int i = 0; i < 16; i++) d[i] = 0.0f;

    #pragma unroll
    for (int c = 0; c < N_CLAUSES; c++) {
        float w  = c_ucw[c];
        float e0 = __expf(-x[c]), e1 = __expf(x[c + 1]), e2 = __expf(x[c + 2]);
        float inv = __frcp_rn(e0 + e1 + e2);
        d[c]     -= w * e0 * inv;
        d[c + 1] += w * e1 * inv;
        d[c + 2] += w * e2 * inv;
    }

    float u[16];
    #pragma unroll
    for (int i = 0; i < 16; i++) u[i] = x[i] + d[i];

    stg_v8(out_u + (size_t)n * 16,     u);
    stg_v8(out_u + (size_t)n * 16 + 8, u + 8);

    __half2 h[4];
    #pragma unroll
    for (int q = 0; q < 4; q++)
        h[q] = __floats2half2_rn(u[2*q], u[2*q+1]);
    uint4 pk;
    memcpy(&pk, h, 16);
    reinterpret_cast<uint4*>(g_u16)[n] = pk;
}

// ---------------------------------------------------------------------------
// Stage 2 helpers
// ---------------------------------------------------------------------------
// No "memory" clobber: REDs are no-return, out_u is never read here, g_u16 is
// read-only.  volatile pins the op; the compiler may schedule around it.
__device__ __forceinline__ void red_add_v4(float* ptr, float a, float b, float c, float d) {
    asm volatile("red.global.add.v4.f32 [%0], {%1,%2,%3,%4};"
                 :: "l"(ptr), "f"(a), "f"(b), "f"(c), "f"(d));
}

__device__ __forceinline__ void unpack8(uint4 raw, float* u) {
    __half2 h[4];
    memcpy(h, &raw, 16);
    #pragma unroll
    for (int q = 0; q < 4; q++) {
        float2 f = __half22float2(h[q]);
        u[2*q]   = f.x;
        u[2*q+1] = f.y;
    }
}

__device__ __forceinline__ void do_edge(
    uint4 raw1, uint4 raw2, const float* b,
    int i1, int i2,
    float* __restrict__ out_u, float* ob)
{
    float u1[8], u2[8];
    unpack8(raw1, u1);
    unpack8(raw2, u2);

    float eb[4];
    #pragma unroll
    for (int j = 0; j < 4; j++) eb[j] = __expf(b[j]);

    float du1[8], du2[8], db[4] = {0.f, 0.f, 0.f, 0.f};

    #pragma unroll
    for (int c = 0; c < N_CLAUSES; c++) {
        float e0 = __expf(-u1[c]);
        float e2 = __expf(u2[c]);
        float e1 = eb[c & 3];
        float inv = __frcp_rn(e0 + e1 + e2);
        float wi  = c_bcw[c] * inv;
        du1[c]    = -wi * e0;
        db[c & 3] +=  wi * e1;
        du2[c]    =  wi * e2;
    }

    #pragma unroll
    for (int j = 0; j < 4; j++) ob[j] = b[j] + db[j];

    // REDs interleaved across node sides (R9 winner ordering).
    red_add_v4(out_u + (size_t)i1 * N_UNARY,     du1[0], du1[1], du1[2], du1[3]);
    red_add_v4(out_u + (size_t)i2 * N_UNARY,     du2[0], du2[1], du2[2], du2[3]);
    red_add_v4(out_u + (size_t)i1 * N_UNARY + 4, du1[4], du1[5], du1[6], du1[7]);
    red_add_v4(out_u + (size_t)i2 * N_UNARY + 4, du2[4], du2[5], du2[6], du2[7]);
}

// ---------------------------------------------------------------------------
// Stage 2: two edges per thread (ILP-2), 256-thread CTAs x 4 CTAs/SM (R12
// winner config).  binary/out_b as single 256-bit ops per thread.
// 1.6M / 512 = 3125 exact blocks: no tail branch.
// ---------------------------------------------------------------------------
__global__ void __launch_bounds__(256, 4) edge_kernel(
    const float* __restrict__ binary,
    const int*   __restrict__ index1,
    const int*   __restrict__ index2,
    float* __restrict__ out_u,
    float* __restrict__ out_b)
{
    int t = blockIdx.x * blockDim.x + threadIdx.x;

    int2 i1p = __ldcs(reinterpret_cast<const int2*>(index1) + t);
    int2 i2p = __ldcs(reinterpret_cast<const int2*>(index2) + t);

    // all 4 divergent gathers in flight (MLP=4)
    const uint4* gu = reinterpret_cast<const uint4*>(g_u16);
    uint4 rA1 = __ldg(gu + i1p.x);
    uint4 rA2 = __ldg(gu + i2p.x);
    uint4 rB1 = __ldg(gu + i1p.y);
    uint4 rB2 = __ldg(gu + i2p.y);

    // one 256-bit streaming load covers binary for both edges
    float bb[8];
    ldg_v8_cs(binary + (size_t)t * 8, bb);

    float ob[8];
    do_edge(rA1, rA2, bb,     i1p.x, i2p.x, out_u, ob);
    do_edge(rB1, rB2, bb + 4, i1p.y, i2p.y, out_u, ob + 4);

    // one 256-bit streaming store covers out_b for both edges
    stg_v8_cs(out_b + (size_t)t * 8, ob);
}

// ---------------------------------------------------------------------------
// Inputs (metadata order): unary[1.6M f32], binary[6.4M f32], unary_cw[8],
// binary_cw[8], index1[1.6M i32], index2[1.6M i32].
// Output: [u+delta_up (100000*16), binary+delta_bp (1.6M*4)] concatenated.
// ---------------------------------------------------------------------------
extern "C" void kernel_launch(void* const* d_in, const int* in_sizes, int n_in,
                              void* d_out, int out_size)
{
    const float* unary     = (const float*)d_in[0];
    const float* binary    = (const float*)d_in[1];
    const float* unary_cw  = (const float*)d_in[2];
    const float* binary_cw = (const float*)d_in[3];
    const int*   index1    = (const int*)d_in[4];
    const int*   index2    = (const int*)d_in[5];

    float* out_u = (float*)d_out;
    float* out_b = out_u + (size_t)N_NODES * N_UNARY;

    // Capturable D2D memcpy nodes: clause weights -> constant bank.
    cudaMemcpyToSymbolAsync(c_ucw, unary_cw,  8 * sizeof(float), 0,
                            cudaMemcpyDeviceToDevice);
    cudaMemcpyToSymbolAsync(c_bcw, binary_cw, 8 * sizeof(float), 0,
                            cudaMemcpyDeviceToDevice);

    node_kernel<<<(N_NODES + 255) / 256, 256>>>(unary, out_u);
    edge_kernel<<<N_EDGES / 512, 256>>>(binary, index1, index2,
                                        out_u, out_b);
}

// round 16
// speedup vs baseline: 1.0693x; 1.0693x over previous
#include <cuda_runtime.h>
#include <cuda_fp16.h>
#include <string.h>

#define N_NODES   100000
#define N_EDGES   1600000
#define N_UNARY   16
#define N_BIN     4
#define N_CLAUSES 8

// Edge-stage gather table: u[:, 0:8] packed as fp16 (16 B per node row).
// 1.6 MB -> fully L2-resident; one divergent LDG.128 per gather side.
__device__ __half2 g_u16[N_NODES * 4];

// ---------------------------------------------------------------------------
// 256-bit coalesced ops (sm_100+)
// ---------------------------------------------------------------------------
__device__ __forceinline__ void ldg_v8(const float* __restrict__ p, float* r) {
    asm volatile("ld.global.nc.v8.f32 {%0,%1,%2,%3,%4,%5,%6,%7}, [%8];"
                 : "=f"(r[0]), "=f"(r[1]), "=f"(r[2]), "=f"(r[3]),
                   "=f"(r[4]), "=f"(r[5]), "=f"(r[6]), "=f"(r[7])
                 : "l"(p));
}
__device__ __forceinline__ void ldg_v8_cs(const float* __restrict__ p, float* r) {
    asm volatile("ld.global.cs.v8.f32 {%0,%1,%2,%3,%4,%5,%6,%7}, [%8];"
                 : "=f"(r[0]), "=f"(r[1]), "=f"(r[2]), "=f"(r[3]),
                   "=f"(r[4]), "=f"(r[5]), "=f"(r[6]), "=f"(r[7])
                 : "l"(p));
}
__device__ __forceinline__ void stg_v8(float* p, const float* r) {
    asm volatile("st.global.v8.f32 [%0], {%1,%2,%3,%4,%5,%6,%7,%8};"
                 :: "l"(p),
                    "f"(r[0]), "f"(r[1]), "f"(r[2]), "f"(r[3]),
                    "f"(r[4]), "f"(r[5]), "f"(r[6]), "f"(r[7]) : "memory");
}
__device__ __forceinline__ void stg_v8_cs(float* p, const float* r) {
    asm volatile("st.global.cs.v8.f32 [%0], {%1,%2,%3,%4,%5,%6,%7,%8};"
                 :: "l"(p),
                    "f"(r[0]), "f"(r[1]), "f"(r[2]), "f"(r[3]),
                    "f"(r[4]), "f"(r[5]), "f"(r[6]), "f"(r[7]) : "memory");
}

// ---------------------------------------------------------------------------
// Stage 1: u = unary + KENN(unary).  v8 streams (R13 winner) + v8 weight load.
// ---------------------------------------------------------------------------
__global__ void __launch_bounds__(256) node_kernel(
    const float* __restrict__ unary,
    const float* __restrict__ unary_cw,
    float* __restrict__ out_u)
{
    int n = blockIdx.x * blockDim.x + threadIdx.x;
    if (n >= N_NODES) return;

    float x[16];
    ldg_v8(unary + (size_t)n * 16,     x);
    ldg_v8(unary + (size_t)n * 16 + 8, x + 8);

    float w[8];
    ldg_v8(unary_cw, w);   // all 8 clause weights in ONE uniform LSU op

    float d[16];
    #pragma unroll
    for (int i = 0; i < 16; i++) d[i] = 0.0f;

    #pragma unroll
    for (int c = 0; c < N_CLAUSES; c++) {
        float e0 = __expf(-x[c]), e1 = __expf(x[c + 1]), e2 = __expf(x[c + 2]);
        float inv = __frcp_rn(e0 + e1 + e2);
        d[c]     -= w[c] * e0 * inv;
        d[c + 1] += w[c] * e1 * inv;
        d[c + 2] += w[c] * e2 * inv;
    }

    float u[16];
    #pragma unroll
    for (int i = 0; i < 16; i++) u[i] = x[i] + d[i];

    stg_v8(out_u + (size_t)n * 16,     u);
    stg_v8(out_u + (size_t)n * 16 + 8, u + 8);

    __half2 h[4];
    #pragma unroll
    for (int q = 0; q < 4; q++)
        h[q] = __floats2half2_rn(u[2*q], u[2*q+1]);
    uint4 pk;
    memcpy(&pk, h, 16);
    reinterpret_cast<uint4*>(g_u16)[n] = pk;
}

// ---------------------------------------------------------------------------
// Stage 2 helpers
// ---------------------------------------------------------------------------
// No "memory" clobber: REDs are no-return, out_u is never read here, g_u16 is
// read-only.  volatile pins the op; the compiler may schedule around it.
__device__ __forceinline__ void red_add_v4(float* ptr, float a, float b, float c, float d) {
    asm volatile("red.global.add.v4.f32 [%0], {%1,%2,%3,%4};"
                 :: "l"(ptr), "f"(a), "f"(b), "f"(c), "f"(d));
}

__device__ __forceinline__ void unpack8(uint4 raw, float* u) {
    __half2 h[4];
    memcpy(h, &raw, 16);
    #pragma unroll
    for (int q = 0; q < 4; q++) {
        float2 f = __half22float2(h[q]);
        u[2*q]   = f.x;
        u[2*q+1] = f.y;
    }
}

__device__ __forceinline__ void do_edge(
    uint4 raw1, uint4 raw2, const float* b, const float* w,
    int i1, int i2,
    float* __restrict__ out_u, float* ob)
{
    float u1[8], u2[8];
    unpack8(raw1, u1);
    unpack8(raw2, u2);

    float eb[4];
    #pragma unroll
    for (int j = 0; j < 4; j++) eb[j] = __expf(b[j]);

    float du1[8], du2[8], db[4] = {0.f, 0.f, 0.f, 0.f};

    #pragma unroll
    for (int c = 0; c < N_CLAUSES; c++) {
        float e0 = __expf(-u1[c]);
        float e2 = __expf(u2[c]);
        float e1 = eb[c & 3];
        float inv = __frcp_rn(e0 + e1 + e2);
        float wi  = w[c] * inv;
        du1[c]    = -wi * e0;
        db[c & 3] +=  wi * e1;
        du2[c]    =  wi * e2;
    }

    #pragma unroll
    for (int j = 0; j < 4; j++) ob[j] = b[j] + db[j];

    // REDs interleaved across node sides (R9 winner ordering).
    red_add_v4(out_u + (size_t)i1 * N_UNARY,     du1[0], du1[1], du1[2], du1[3]);
    red_add_v4(out_u + (size_t)i2 * N_UNARY,     du2[0], du2[1], du2[2], du2[3]);
    red_add_v4(out_u + (size_t)i1 * N_UNARY + 4, du1[4], du1[5], du1[6], du1[7]);
    red_add_v4(out_u + (size_t)i2 * N_UNARY + 4, du2[4], du2[5], du2[6], du2[7]);
}

// ---------------------------------------------------------------------------
// Stage 2: two edges per thread (ILP-2), 256-thread CTAs x 4 CTAs/SM (R12
// winner config).  binary/out_b as single 256-bit ops per thread; clause
// weights fetched in one v8 uniform load.
// 1.6M / 512 = 3125 exact blocks: no tail branch.
// ---------------------------------------------------------------------------
__global__ void __launch_bounds__(256, 4) edge_kernel(
    const float* __restrict__ binary,
    const float* __restrict__ binary_cw,
    const int*   __restrict__ index1,
    const int*   __restrict__ index2,
    float* __restrict__ out_u,
    float* __restrict__ out_b)
{
    int t = blockIdx.x * blockDim.x + threadIdx.x;

    int2 i1p = __ldcs(reinterpret_cast<const int2*>(index1) + t);
    int2 i2p = __ldcs(reinterpret_cast<const int2*>(index2) + t);

    // all 4 divergent gathers in flight (MLP=4)
    const uint4* gu = reinterpret_cast<const uint4*>(g_u16);
    uint4 rA1 = __ldg(gu + i1p.x);
    uint4 rA2 = __ldg(gu + i2p.x);
    uint4 rB1 = __ldg(gu + i1p.y);
    uint4 rB2 = __ldg(gu + i2p.y);

    // one 256-bit streaming load covers binary for both edges
    float bb[8];
    ldg_v8_cs(binary + (size_t)t * 8, bb);

    // all 8 clause weights in ONE uniform LSU op (was 8 scalar __ldg)
    float w[8];
    ldg_v8(binary_cw, w);

    float ob[8];
    do_edge(rA1, rA2, bb,     w, i1p.x, i2p.x, out_u, ob);
    do_edge(rB1, rB2, bb + 4, w, i1p.y, i2p.y, out_u, ob + 4);

    // one 256-bit streaming store covers out_b for both edges
    stg_v8_cs(out_b + (size_t)t * 8, ob);
}

// ---------------------------------------------------------------------------
// Inputs (metadata order): unary[1.6M f32], binary[6.4M f32], unary_cw[8],
// binary_cw[8], index1[1.6M i32], index2[1.6M i32].
// Output: [u+delta_up (100000*16), binary+delta_bp (1.6M*4)] concatenated.
// ---------------------------------------------------------------------------
extern "C" void kernel_launch(void* const* d_in, const int* in_sizes, int n_in,
                              void* d_out, int out_size)
{
    const float* unary     = (const float*)d_in[0];
    const float* binary    = (const float*)d_in[1];
    const float* unary_cw  = (const float*)d_in[2];
    const float* binary_cw = (const float*)d_in[3];
    const int*   index1    = (const int*)d_in[4];
    const int*   index2    = (const int*)d_in[5];

    float* out_u = (float*)d_out;
    float* out_b = out_u + (size_t)N_NODES * N_UNARY;

    node_kernel<<<(N_NODES + 255) / 256, 256>>>(unary, unary_cw, out_u);
    edge_kernel<<<N_EDGES / 512, 256>>>(binary, binary_cw, index1, index2,
                                        out_u, out_b);
}

// round 17
// speedup vs baseline: 1.0722x; 1.0027x over previous
#include <cuda_runtime.h>
#include <cuda_fp16.h>
#include <string.h>

#define N_NODES   100000
#define N_EDGES   1600000
#define N_UNARY   16
#define N_BIN     4
#define N_CLAUSES 8

// Edge-stage gather table: u[:, 0:8] packed as fp16 (16 B per node row).
// 1.6 MB -> fully L2-resident; one divergent LDG.128 per gather side.
__device__ __half2 g_u16[N_NODES * 4];

// ---------------------------------------------------------------------------
// 256-bit coalesced ops (sm_100+)
// ---------------------------------------------------------------------------
__device__ __forceinline__ void ldg_v8(const float* __restrict__ p, float* r) {
    asm volatile("ld.global.nc.v8.f32 {%0,%1,%2,%3,%4,%5,%6,%7}, [%8];"
                 : "=f"(r[0]), "=f"(r[1]), "=f"(r[2]), "=f"(r[3]),
                   "=f"(r[4]), "=f"(r[5]), "=f"(r[6]), "=f"(r[7])
                 : "l"(p));
}
__device__ __forceinline__ void ldg_v8_cs(const float* __restrict__ p, float* r) {
    asm volatile("ld.global.cs.v8.f32 {%0,%1,%2,%3,%4,%5,%6,%7}, [%8];"
                 : "=f"(r[0]), "=f"(r[1]), "=f"(r[2]), "=f"(r[3]),
                   "=f"(r[4]), "=f"(r[5]), "=f"(r[6]), "=f"(r[7])
                 : "l"(p));
}
__device__ __forceinline__ void stg_v8(float* p, const float* r) {
    asm volatile("st.global.v8.f32 [%0], {%1,%2,%3,%4,%5,%6,%7,%8};"
                 :: "l"(p),
                    "f"(r[0]), "f"(r[1]), "f"(r[2]), "f"(r[3]),
                    "f"(r[4]), "f"(r[5]), "f"(r[6]), "f"(r[7]) : "memory");
}
__device__ __forceinline__ void stg_v8_cs(float* p, const float* r) {
    asm volatile("st.global.cs.v8.f32 [%0], {%1,%2,%3,%4,%5,%6,%7,%8};"
                 :: "l"(p),
                    "f"(r[0]), "f"(r[1]), "f"(r[2]), "f"(r[3]),
                    "f"(r[4]), "f"(r[5]), "f"(r[6]), "f"(r[7]) : "memory");
}

// ---------------------------------------------------------------------------
// Stage 1: u = unary + KENN(unary).  v8 streams + v8 weight load (R16 winner).
// ---------------------------------------------------------------------------
__global__ void __launch_bounds__(256) node_kernel(
    const float* __restrict__ unary,
    const float* __restrict__ unary_cw,
    float* __restrict__ out_u)
{
    int n = blockIdx.x * blockDim.x + threadIdx.x;
    if (n >= N_NODES) return;

    float x[16];
    ldg_v8(unary + (size_t)n * 16,     x);
    ldg_v8(unary + (size_t)n * 16 + 8, x + 8);

    float w[8];
    ldg_v8(unary_cw, w);   // all 8 clause weights in ONE uniform LSU op

    float d[16];
    #pragma unroll
    for (int i = 0; i < 16; i++) d[i] = 0.0f;

    #pragma unroll
    for (int c = 0; c < N_CLAUSES; c++) {
        float e0 = __expf(-x[c]), e1 = __expf(x[c + 1]), e2 = __expf(x[c + 2]);
        float inv = __frcp_rn(e0 + e1 + e2);
        d[c]     -= w[c] * e0 * inv;
        d[c + 1] += w[c] * e1 * inv;
        d[c + 2] += w[c] * e2 * inv;
    }

    float u[16];
    #pragma unroll
    for (int i = 0; i < 16; i++) u[i] = x[i] + d[i];

    stg_v8(out_u + (size_t)n * 16,     u);
    stg_v8(out_u + (size_t)n * 16 + 8, u + 8);

    __half2 h[4];
    #pragma unroll
    for (int q = 0; q < 4; q++)
        h[q] = __floats2half2_rn(u[2*q], u[2*q+1]);
    uint4 pk;
    memcpy(&pk, h, 16);
    reinterpret_cast<uint4*>(g_u16)[n] = pk;
}

// ---------------------------------------------------------------------------
// Stage 2 helpers
// ---------------------------------------------------------------------------
// No "memory" clobber: REDs are no-return, out_u is never read here, g_u16 is
// read-only.  volatile pins the op; the compiler may schedule around it.
__device__ __forceinline__ void red_add_v4(float* ptr, const float* v) {
    asm volatile("red.global.add.v4.f32 [%0], {%1,%2,%3,%4};"
                 :: "l"(ptr), "f"(v[0]), "f"(v[1]), "f"(v[2]), "f"(v[3]));
}

__device__ __forceinline__ void unpack8(uint4 raw, float* u) {
    __half2 h[4];
    memcpy(h, &raw, 16);
    #pragma unroll
    for (int q = 0; q < 4; q++) {
        float2 f = __half22float2(h[q]);
        u[2*q]   = f.x;
        u[2*q+1] = f.y;
    }
}

// Compute-only phase of one edge: produces du1/du2 (scatter deltas) and ob
// (binary output row).  No memory traffic.
__device__ __forceinline__ void edge_compute(
    uint4 raw1, uint4 raw2, const float* b, const float* w,
    float* du1, float* du2, float* ob)
{
    float u1[8], u2[8];
    unpack8(raw1, u1);
    unpack8(raw2, u2);

    float eb[4];
    #pragma unroll
    for (int j = 0; j < 4; j++) eb[j] = __expf(b[j]);

    float db[4] = {0.f, 0.f, 0.f, 0.f};

    #pragma unroll
    for (int c = 0; c < N_CLAUSES; c++) {
        float e0 = __expf(-u1[c]);
        float e2 = __expf(u2[c]);
        float e1 = eb[c & 3];
        float inv = __frcp_rn(e0 + e1 + e2);
        float wi  = w[c] * inv;
        du1[c]    = -wi * e0;
        db[c & 3] +=  wi * e1;
        du2[c]    =  wi * e2;
    }

    #pragma unroll
    for (int j = 0; j < 4; j++) ob[j] = b[j] + db[j];
}

// ---------------------------------------------------------------------------
// Stage 2: two edges per thread (ILP-2), 256-thread CTAs x 4 CTAs/SM.
// Both edges computed first; all 8 REDs issued as one interleaved burst
// (max address dispersal per lane at the LTS, uninterrupted LSU issue).
// 1.6M / 512 = 3125 exact blocks: no tail branch.
// ---------------------------------------------------------------------------
__global__ void __launch_bounds__(256, 4) edge_kernel(
    const float* __restrict__ binary,
    const float* __restrict__ binary_cw,
    const int*   __restrict__ index1,
    const int*   __restrict__ index2,
    float* __restrict__ out_u,
    float* __restrict__ out_b)
{
    int t = blockIdx.x * blockDim.x + threadIdx.x;

    int2 i1p = __ldcs(reinterpret_cast<const int2*>(index1) + t);
    int2 i2p = __ldcs(reinterpret_cast<const int2*>(index2) + t);

    // all 4 divergent gathers in flight (MLP=4)
    const uint4* gu = reinterpret_cast<const uint4*>(g_u16);
    uint4 rA1 = __ldg(gu + i1p.x);
    uint4 rA2 = __ldg(gu + i2p.x);
    uint4 rB1 = __ldg(gu + i1p.y);
    uint4 rB2 = __ldg(gu + i2p.y);

    // one 256-bit streaming load covers binary for both edges
    float bb[8];
    ldg_v8_cs(binary + (size_t)t * 8, bb);

    // all 8 clause weights in ONE uniform LSU op
    float w[8];
    ldg_v8(binary_cw, w);

    // compute both edges fully (no memory ops in between)
    float duA1[8], duA2[8], duB1[8], duB2[8], ob[8];
    edge_compute(rA1, rA2, bb,     w, duA1, duA2, ob);
    edge_compute(rB1, rB2, bb + 4, w, duB1, duB2, ob + 4);

    // coalesced result store first, then the RED burst
    stg_v8_cs(out_b + (size_t)t * 8, ob);

    // 8 REDs, interleaved across edges and node sides: each lane's
    // consecutive ops target 4 distinct random lines before any revisit.
    float* pA1 = out_u + (size_t)i1p.x * N_UNARY;
    float* pA2 = out_u + (size_t)i2p.x * N_UNARY;
    float* pB1 = out_u + (size_t)i1p.y * N_UNARY;
    float* pB2 = out_u + (size_t)i2p.y * N_UNARY;

    red_add_v4(pA1,     duA1);
    red_add_v4(pA2,     duA2);
    red_add_v4(pB1,     duB1);
    red_add_v4(pB2,     duB2);
    red_add_v4(pA1 + 4, duA1 + 4);
    red_add_v4(pA2 + 4, duA2 + 4);
    red_add_v4(pB1 + 4, duB1 + 4);
    red_add_v4(pB2 + 4, duB2 + 4);
}

// ---------------------------------------------------------------------------
// Inputs (metadata order): unary[1.6M f32], binary[6.4M f32], unary_cw[8],
// binary_cw[8], index1[1.6M i32], index2[1.6M i32].
// Output: [u+delta_up (100000*16), binary+delta_bp (1.6M*4)] concatenated.
// ---------------------------------------------------------------------------
extern "C" void kernel_launch(void* const* d_in, const int* in_sizes, int n_in,
                              void* d_out, int out_size)
{
    const float* unary     = (const float*)d_in[0];
    const float* binary    = (const float*)d_in[1];
    const float* unary_cw  = (const float*)d_in[2];
    const float* binary_cw = (const float*)d_in[3];
    const int*   index1    = (const int*)d_in[4];
    const int*   index2    = (const int*)d_in[5];

    float* out_u = (float*)d_out;
    float* out_b = out_u + (size_t)N_NODES * N_UNARY;

    node_kernel<<<(N_NODES + 255) / 256, 256>>>(unary, unary_cw, out_u);
    edge_kernel<<<N_EDGES / 512, 256>>>(binary, binary_cw, index1, index2,
                                        out_u, out_b);
}